// round 7
// baseline (speedup 1.0000x reference)
#include <cuda_runtime.h>
#include <cuda_bf16.h>

// db4 DWT, single level.
// x:   [B=32, T=16384, C=64] f32
// out: [B=32, TOUT=8190, 2C=128] f32  (approx channels 0..63, detail 64..127)
// out[b, t, c]    = sum_k x[b, refl(2t-1+k), c] * lo[k]
// out[b, t, 64+c] = sum_k x[b, refl(2t-1+k), c] * hi[k]
// refl: j<0 -> -j ; j>=T -> 2T-2-j   (only hits j=-1 and j=T)

#define T_IN   16384
#define T_OUT  8190
#define C_IN   64
#define TPER   10          // 8190 = 819 * 10, exact
#define NTILES 819

__device__ __forceinline__ int refl(int j) {
    j = (j < 0) ? -j : j;
    j = (j >= T_IN) ? (2 * T_IN - 2 - j) : j;
    return j;
}

__device__ __forceinline__ float4 fma4(float s, float4 v, float4 acc) {
    acc.x = fmaf(s, v.x, acc.x);
    acc.y = fmaf(s, v.y, acc.y);
    acc.z = fmaf(s, v.z, acc.z);
    acc.w = fmaf(s, v.w, acc.w);
    return acc;
}

__global__ __launch_bounds__(256, 4)
void dwt_db4_kernel(const float* __restrict__ x,
                    const float* __restrict__ dec_lo,
                    const float* __restrict__ dec_hi,
                    float* __restrict__ out) {
    const int c4   = threadIdx.x;                              // 0..15 float4 channel group
    const int tile = blockIdx.x * blockDim.y + threadIdx.y;    // time tile
    const int b    = blockIdx.y;
    if (tile >= NTILES) return;
    const int t0 = tile * TPER;

    // Filters: uniform-address broadcast loads (L1-cached after first warp).
    float l[8], h[8];
#pragma unroll
    for (int k = 0; k < 8; ++k) {
        l[k] = __ldg(dec_lo + k);
        h[k] = __ldg(dec_hi + k);
    }

    // Base pointers (float4 granularity). x row = 16 float4; out row = 32 float4.
    const float4* xb = reinterpret_cast<const float4*>(x)
                     + (size_t)b * T_IN * (C_IN / 4) + c4;
    float4* ob = reinterpret_cast<float4*>(out)
               + (size_t)b * T_OUT * (2 * C_IN / 4) + c4;

    // Sliding window of 8 time samples (float4 each).
    float4 w[8];
#pragma unroll
    for (int k = 0; k < 6; ++k) {
        const int j = refl(2 * t0 - 1 + k);
        w[k] = __ldg(xb + (size_t)j * (C_IN / 4));
    }

#pragma unroll
    for (int i = 0; i < TPER; ++i) {
        const int t = t0 + i;
        const int j = 2 * t + 5;
        w[6] = __ldg(xb + (size_t)refl(j)     * (C_IN / 4));
        w[7] = __ldg(xb + (size_t)refl(j + 1) * (C_IN / 4));

        float4 a = make_float4(0.f, 0.f, 0.f, 0.f);
        float4 d = make_float4(0.f, 0.f, 0.f, 0.f);
#pragma unroll
        for (int k = 0; k < 8; ++k) {
            a = fma4(l[k], w[k], a);
            d = fma4(h[k], w[k], d);
        }

        ob[(size_t)t * 32]      = a;   // approx: channels [0,64)
        ob[(size_t)t * 32 + 16] = d;   // detail: channels [64,128)

#pragma unroll
        for (int k = 0; k < 6; ++k) w[k] = w[k + 2];
    }
}

extern "C" void kernel_launch(void* const* d_in, const int* in_sizes, int n_in,
                              void* d_out, int out_size) {
    const float* x      = (const float*)d_in[0];
    const float* dec_lo = (const float*)d_in[1];
    const float* dec_hi = (const float*)d_in[2];
    float* out          = (float*)d_out;

    dim3 block(16, 8);                               // 256 threads: 16 c4-groups x 8 tiles
    dim3 grid((NTILES + 7) / 8, 32);                 // 103 x B
    dwt_db4_kernel<<<grid, block>>>(x, dec_lo, dec_hi, out);
}